// round 1
// baseline (speedup 1.0000x reference)
#include <cuda_runtime.h>

#define HNUM 16
#define NSEQ 2048
#define DDIM 64
#define CHK  128
#define NC   (NSEQ / CHK)      // 16 chunks
#define NB   (HNUM * NC)       // 256 (head, chunk) tiles
#define EPSV 1e-6f

#define SKT_STRIDE 129
#define SA_STRIDE  130

// Scratch: per-(head,chunk) KV state (64x64) and K feature-sum (64).
// Phase 1 writes per-chunk sums; phase 2 converts in place to EXCLUSIVE prefix.
__device__ float g_KV[(size_t)NB * DDIM * DDIM];   // 4 MB
__device__ float g_Kz[(size_t)NB * DDIM];          // 256 KB

__device__ __forceinline__ float fmap(float x) {
    // elu(x) + 1 : x>0 -> x+1 ; x<=0 -> exp(x)
    return x > 0.f ? x + 1.f : __expf(x);
}

// ---------------------------------------------------------------------------
// Phase 1: per-chunk KV = phiK^T V  (64x64)  and Kz = colsum(phiK)
// grid = NB, block = 256
// ---------------------------------------------------------------------------
__global__ void __launch_bounds__(256) lin_phase1(const float* __restrict__ Kg,
                                                  const float* __restrict__ Vg) {
    extern __shared__ float sm[];
    float* sK = sm;               // CHK*DDIM phiK
    float* sV = sm + CHK * DDIM;  // CHK*DDIM
    const int tid = threadIdx.x;
    const size_t base = (size_t)blockIdx.x * (CHK * DDIM);

    #pragma unroll
    for (int s = 0; s < (CHK * DDIM) / 256; s++) {
        int i = tid + s * 256;
        sK[i] = fmap(Kg[base + i]);
        sV[i] = Vg[base + i];
    }
    __syncthreads();

    // 4x4 register tile: 16 d-groups x 16 e-groups
    const int d0 = (tid >> 4) * 4;
    const int e0 = (tid & 15) * 4;
    float acc[4][4] = {};
    #pragma unroll 4
    for (int m = 0; m < CHK; m++) {
        float4 kf = *(const float4*)&sK[m * DDIM + d0];
        float4 vf = *(const float4*)&sV[m * DDIM + e0];
        float kk[4] = {kf.x, kf.y, kf.z, kf.w};
        float vv[4] = {vf.x, vf.y, vf.z, vf.w};
        #pragma unroll
        for (int a = 0; a < 4; a++)
            #pragma unroll
            for (int b = 0; b < 4; b++)
                acc[a][b] += kk[a] * vv[b];
    }

    float* kvo = g_KV + (size_t)blockIdx.x * (DDIM * DDIM);
    #pragma unroll
    for (int a = 0; a < 4; a++) {
        float4 o = make_float4(acc[a][0], acc[a][1], acc[a][2], acc[a][3]);
        *(float4*)&kvo[(d0 + a) * DDIM + e0] = o;
    }

    if (tid < DDIM) {
        float s = 0.f;
        #pragma unroll 8
        for (int m = 0; m < CHK; m++) s += sK[m * DDIM + tid];
        g_Kz[(size_t)blockIdx.x * DDIM + tid] = s;
    }
}

// ---------------------------------------------------------------------------
// Phase 2: in-place exclusive prefix over chunks (per head).
// grid = HNUM, block = 512
// ---------------------------------------------------------------------------
__global__ void __launch_bounds__(512) lin_phase2() {
    const int h = blockIdx.x;
    const int tid = threadIdx.x;

    for (int idx = tid; idx < DDIM * DDIM; idx += 512) {
        float run = 0.f;
        #pragma unroll
        for (int c = 0; c < NC; c++) {
            float* p = g_KV + ((size_t)(h * NC + c)) * (DDIM * DDIM) + idx;
            float v = *p;
            *p = run;
            run += v;
        }
    }
    if (tid < DDIM) {
        float run = 0.f;
        #pragma unroll
        for (int c = 0; c < NC; c++) {
            float* p = g_Kz + (size_t)(h * NC + c) * DDIM + tid;
            float v = *p;
            *p = run;
            run += v;
        }
    }
}

// ---------------------------------------------------------------------------
// Phase 3: per chunk:
//   A      = phiQ @ phiK^T          (128x128, causal-masked)
//   den[m] = rowsum(A_masked) + phiQ[m].z_excl + EPS
//   out    = (A_masked @ V + phiQ @ S_excl) / den
// grid = NB, block = 256
// ---------------------------------------------------------------------------
__global__ void __launch_bounds__(256) lin_phase3(const float* __restrict__ Qg,
                                                  const float* __restrict__ Kg,
                                                  const float* __restrict__ Vg,
                                                  float* __restrict__ Og) {
    extern __shared__ float sm[];
    float* sQ   = sm;                         // CHK*DDIM         (8192)
    float* sKt  = sQ  + CHK * DDIM;           // DDIM*SKT_STRIDE  (8256) transposed phiK
    float* sV   = sKt + DDIM * SKT_STRIDE;    // CHK*DDIM         (8192)
    float* sS   = sV  + CHK * DDIM;           // DDIM*DDIM        (4096)
    float* sA   = sS  + DDIM * DDIM;          // CHK*SA_STRIDE    (16640)
    float* sZ   = sA  + CHK * SA_STRIDE;      // DDIM
    float* sDen = sZ  + DDIM;                 // CHK

    const int tid = threadIdx.x;
    const size_t base = (size_t)blockIdx.x * (CHK * DDIM);

    #pragma unroll
    for (int s = 0; s < (CHK * DDIM) / 256; s++) {
        int i = tid + s * 256;
        int m = i >> 6;
        int d = i & 63;
        sQ[i] = fmap(Qg[base + i]);
        sKt[d * SKT_STRIDE + m] = fmap(Kg[base + i]);   // conflict-free transpose (stride 129)
        sV[i] = Vg[base + i];
    }
    const float* Sg = g_KV + (size_t)blockIdx.x * (DDIM * DDIM);
    for (int i = tid; i < DDIM * DDIM; i += 256) sS[i] = Sg[i];
    if (tid < DDIM) sZ[tid] = g_Kz[(size_t)blockIdx.x * DDIM + tid];
    __syncthreads();

    // --- A-phase: 8x8 tile per thread, 16x16 thread grid over 128x128 ---
    {
        const int m0 = (tid >> 4) * 8;
        const int j0 = (tid & 15) * 8;
        float acc[8][8] = {};
        for (int d = 0; d < DDIM; d++) {
            float qf[8], kf[8];
            #pragma unroll
            for (int a = 0; a < 8; a++) qf[a] = sQ[(m0 + a) * DDIM + d];
            #pragma unroll
            for (int b = 0; b < 8; b++) kf[b] = sKt[d * SKT_STRIDE + j0 + b];
            #pragma unroll
            for (int a = 0; a < 8; a++)
                #pragma unroll
                for (int b = 0; b < 8; b++)
                    acc[a][b] += qf[a] * kf[b];
        }
        #pragma unroll
        for (int a = 0; a < 8; a++)
            #pragma unroll
            for (int b = 0; b < 8; b++)
                sA[(m0 + a) * SA_STRIDE + j0 + b] =
                    (j0 + b <= m0 + a) ? acc[a][b] : 0.f;
    }
    __syncthreads();

    // --- denominator ---
    if (tid < CHK) {
        float s = EPSV;
        #pragma unroll 8
        for (int j = 0; j < CHK; j++) s += sA[tid * SA_STRIDE + j];
        #pragma unroll 8
        for (int d = 0; d < DDIM; d++) s += sQ[tid * DDIM + d] * sZ[d];
        sDen[tid] = 1.f / s;
    }
    __syncthreads();

    // --- B-phase: out = A@V + phiQ@S, 8x4 tile per thread ---
    {
        const int m0 = (tid >> 4) * 8;
        const int e0 = (tid & 15) * 4;
        float acc[8][4] = {};
        for (int k = 0; k < CHK; k++) {
            float4 vf = *(const float4*)&sV[k * DDIM + e0];
            #pragma unroll
            for (int a = 0; a < 8; a++) {
                float g = sA[(m0 + a) * SA_STRIDE + k];
                acc[a][0] += g * vf.x;
                acc[a][1] += g * vf.y;
                acc[a][2] += g * vf.z;
                acc[a][3] += g * vf.w;
            }
        }
        for (int d = 0; d < DDIM; d++) {
            float4 sf = *(const float4*)&sS[d * DDIM + e0];
            #pragma unroll
            for (int a = 0; a < 8; a++) {
                float q = sQ[(m0 + a) * DDIM + d];
                acc[a][0] += q * sf.x;
                acc[a][1] += q * sf.y;
                acc[a][2] += q * sf.z;
                acc[a][3] += q * sf.w;
            }
        }
        #pragma unroll
        for (int a = 0; a < 8; a++) {
            float inv = sDen[m0 + a];
            float4 o = make_float4(acc[a][0] * inv, acc[a][1] * inv,
                                   acc[a][2] * inv, acc[a][3] * inv);
            *(float4*)&Og[base + (m0 + a) * DDIM + e0] = o;
        }
    }
}

// ---------------------------------------------------------------------------
extern "C" void kernel_launch(void* const* d_in, const int* in_sizes, int n_in,
                              void* d_out, int out_size) {
    const float* Q = (const float*)d_in[0];
    const float* K = (const float*)d_in[1];
    const float* V = (const float*)d_in[2];
    float* O = (float*)d_out;

    const int SMEM1 = 2 * CHK * DDIM * (int)sizeof(float);                 // 64 KB
    const int SMEM3 = (CHK * DDIM * 3 + DDIM * SKT_STRIDE + DDIM * DDIM +
                       CHK * SA_STRIDE + DDIM + CHK) * (int)sizeof(float); // ~178 KB

    cudaFuncSetAttribute(lin_phase1, cudaFuncAttributeMaxDynamicSharedMemorySize, SMEM1);
    cudaFuncSetAttribute(lin_phase3, cudaFuncAttributeMaxDynamicSharedMemorySize, SMEM3);

    lin_phase1<<<NB, 256, SMEM1>>>(K, V);
    lin_phase2<<<HNUM, 512>>>();
    lin_phase3<<<NB, 256, SMEM3>>>(Q, K, V, O);
}

// round 2
// speedup vs baseline: 1.9207x; 1.9207x over previous
#include <cuda_runtime.h>

#define HNUM 16
#define NSEQ 2048
#define DDIM 64
#define CHK  64
#define NC   (NSEQ / CHK)      // 32 chunks
#define NB   (HNUM * NC)       // 512 (head, chunk) tiles
#define EPSV 1e-6f

#define ST 68                  // padded stride for transposed tiles / A

// Scratch: per-(head,chunk) KV state (64x64) and K feature-sum (64).
// Phase 1 writes per-chunk sums; phase 2 converts in place to EXCLUSIVE prefix.
__device__ float g_KV[(size_t)NB * DDIM * DDIM];   // 8 MB
__device__ float g_Kz[(size_t)NB * DDIM];          // 128 KB

__device__ __forceinline__ float fmap(float x) {
    // elu(x) + 1 : x>0 -> x+1 ; x<=0 -> exp(x)
    return x > 0.f ? x + 1.f : __expf(x);
}

// ---------------------------------------------------------------------------
// Phase 1: per-chunk KV = phiK^T V  (64x64)  and Kz = colsum(phiK)
// grid = NB (512), block = 256
// ---------------------------------------------------------------------------
__global__ void __launch_bounds__(256) lin_phase1(const float* __restrict__ Kg,
                                                  const float* __restrict__ Vg) {
    extern __shared__ float sm[];
    float* sK = sm;                    // CHK*DDIM phiK (row-major)
    float* sV = sm + CHK * DDIM;       // CHK*DDIM
    const int tid = threadIdx.x;
    const size_t base = (size_t)blockIdx.x * (CHK * DDIM);

    #pragma unroll
    for (int s = 0; s < 4; s++) {
        int i4 = tid + s * 256;                 // float4 index, 1024 total
        float4 k = ((const float4*)(Kg + base))[i4];
        float4 v = ((const float4*)(Vg + base))[i4];
        k.x = fmap(k.x); k.y = fmap(k.y); k.z = fmap(k.z); k.w = fmap(k.w);
        ((float4*)sK)[i4] = k;
        ((float4*)sV)[i4] = v;
    }
    __syncthreads();

    const int d0 = (tid >> 4) * 4;
    const int e0 = (tid & 15) * 4;
    float acc[4][4] = {};
    #pragma unroll 8
    for (int m = 0; m < CHK; m++) {
        float4 kf = *(const float4*)&sK[m * DDIM + d0];
        float4 vf = *(const float4*)&sV[m * DDIM + e0];
        float kk[4] = {kf.x, kf.y, kf.z, kf.w};
        float vv[4] = {vf.x, vf.y, vf.z, vf.w};
        #pragma unroll
        for (int a = 0; a < 4; a++)
            #pragma unroll
            for (int b = 0; b < 4; b++)
                acc[a][b] += kk[a] * vv[b];
    }

    float* kvo = g_KV + (size_t)blockIdx.x * (DDIM * DDIM);
    #pragma unroll
    for (int a = 0; a < 4; a++)
        *(float4*)&kvo[(d0 + a) * DDIM + e0] =
            make_float4(acc[a][0], acc[a][1], acc[a][2], acc[a][3]);

    if (tid < DDIM) {
        float s = 0.f;
        #pragma unroll 8
        for (int m = 0; m < CHK; m++) s += sK[m * DDIM + tid];
        g_Kz[(size_t)blockIdx.x * DDIM + tid] = s;
    }
}

// ---------------------------------------------------------------------------
// Phase 2: in-place exclusive prefix over 32 chunks (per head).
// grid = 16 heads * 8 parts = 128, block = 512
// ---------------------------------------------------------------------------
__global__ void __launch_bounds__(512) lin_phase2() {
    const int h = blockIdx.x >> 3;
    const int part = blockIdx.x & 7;
    const int idx = part * 512 + threadIdx.x;   // 0..4095

    float run = 0.f;
    #pragma unroll
    for (int c = 0; c < NC; c++) {
        float* p = g_KV + ((size_t)(h * NC + c)) * (DDIM * DDIM) + idx;
        float v = *p;
        *p = run;
        run += v;
    }
    if (part == 0 && threadIdx.x < DDIM) {
        float rz = 0.f;
        #pragma unroll
        for (int c = 0; c < NC; c++) {
            float* p = g_Kz + (size_t)(h * NC + c) * DDIM + threadIdx.x;
            float v = *p;
            *p = rz;
            rz += v;
        }
    }
}

// ---------------------------------------------------------------------------
// Phase 3: per chunk (C=64):
//   A      = phiQ @ phiK^T   (64x64, causal-masked, stored TRANSPOSED)
//   den[m] = rowsum(A) + phiQ[m].z_excl + EPS
//   out    = (A @ V + phiQ @ S_excl) / den
// grid = NB (512), block = 256
// ---------------------------------------------------------------------------
__global__ void __launch_bounds__(256) lin_phase3(const float* __restrict__ Qg,
                                                  const float* __restrict__ Kg,
                                                  const float* __restrict__ Vg,
                                                  float* __restrict__ Og) {
    extern __shared__ float sm[];
    float* sQt  = sm;                   // [d][m] DDIM*ST
    float* sKt  = sQt + DDIM * ST;      // [d][j] DDIM*ST
    float* sV   = sKt + DDIM * ST;      // [k][e] CHK*DDIM
    float* sS   = sV  + CHK * DDIM;     // [d][e] DDIM*DDIM
    float* sAt  = sS  + DDIM * DDIM;    // [k][m] CHK*ST (transposed, masked)
    float* sZ   = sAt + CHK * ST;       // DDIM
    float* sDen = sZ  + DDIM;           // CHK

    const int tid = threadIdx.x;
    const size_t base = (size_t)blockIdx.x * (CHK * DDIM);

    // --- load + feature map + transpose Q,K; V row-major; S,z from scratch ---
    {
        const int m  = tid >> 2;          // 0..63
        const int d0 = (tid & 3) * 16;    // 0,16,32,48
        #pragma unroll
        for (int u = 0; u < 4; u++) {
            int col = d0 + 4 * u;
            float4 q = *(const float4*)(Qg + base + m * DDIM + col);
            float4 k = *(const float4*)(Kg + base + m * DDIM + col);
            float4 v = *(const float4*)(Vg + base + m * DDIM + col);
            sQt[(col + 0) * ST + m] = fmap(q.x);
            sQt[(col + 1) * ST + m] = fmap(q.y);
            sQt[(col + 2) * ST + m] = fmap(q.z);
            sQt[(col + 3) * ST + m] = fmap(q.w);
            sKt[(col + 0) * ST + m] = fmap(k.x);
            sKt[(col + 1) * ST + m] = fmap(k.y);
            sKt[(col + 2) * ST + m] = fmap(k.z);
            sKt[(col + 3) * ST + m] = fmap(k.w);
            *(float4*)&sV[m * DDIM + col] = v;
        }
        const float* Sg = g_KV + (size_t)blockIdx.x * (DDIM * DDIM);
        #pragma unroll
        for (int s = 0; s < 4; s++)
            ((float4*)sS)[tid + s * 256] = ((const float4*)Sg)[tid + s * 256];
        if (tid < DDIM) sZ[tid] = g_Kz[(size_t)blockIdx.x * DDIM + tid];
    }
    __syncthreads();

    const int rbase = (tid >> 4) * 4;   // output rows (m)
    const int cbase = (tid & 15) * 4;   // output cols (j / e)

    // --- A-phase: A[m][j] = sum_d phiQ[m][d] phiK[j][d]; store transposed ---
    {
        float acc[4][4] = {};
        #pragma unroll 8
        for (int d = 0; d < DDIM; d++) {
            float4 qf = *(const float4*)&sQt[d * ST + rbase];
            float4 kf = *(const float4*)&sKt[d * ST + cbase];
            float qq[4] = {qf.x, qf.y, qf.z, qf.w};
            float kk[4] = {kf.x, kf.y, kf.z, kf.w};
            #pragma unroll
            for (int a = 0; a < 4; a++)
                #pragma unroll
                for (int b = 0; b < 4; b++)
                    acc[a][b] += qq[a] * kk[b];
        }
        #pragma unroll
        for (int b = 0; b < 4; b++) {
            int col = cbase + b;
            float4 o;
            o.x = (col <= rbase + 0) ? acc[0][b] : 0.f;
            o.y = (col <= rbase + 1) ? acc[1][b] : 0.f;
            o.z = (col <= rbase + 2) ? acc[2][b] : 0.f;
            o.w = (col <= rbase + 3) ? acc[3][b] : 0.f;
            *(float4*)&sAt[col * ST + rbase] = o;
        }
    }
    __syncthreads();

    // --- denominator ---
    if (tid < CHK) {
        float s = EPSV;
        #pragma unroll 8
        for (int k = 0; k < CHK; k++) s += sAt[k * ST + tid];
        #pragma unroll 8
        for (int d = 0; d < DDIM; d++) s += sQt[d * ST + tid] * sZ[d];
        sDen[tid] = 1.f / s;
    }
    __syncthreads();

    // --- B-phase: out = A@V + phiQ@S ---
    {
        float acc[4][4] = {};
        #pragma unroll 8
        for (int k = 0; k < CHK; k++) {
            float4 af = *(const float4*)&sAt[k * ST + rbase];
            float4 vf = *(const float4*)&sV[k * DDIM + cbase];
            float aa[4] = {af.x, af.y, af.z, af.w};
            float vv[4] = {vf.x, vf.y, vf.z, vf.w};
            #pragma unroll
            for (int a = 0; a < 4; a++)
                #pragma unroll
                for (int b = 0; b < 4; b++)
                    acc[a][b] += aa[a] * vv[b];
        }
        #pragma unroll 8
        for (int d = 0; d < DDIM; d++) {
            float4 qf = *(const float4*)&sQt[d * ST + rbase];
            float4 sf = *(const float4*)&sS[d * DDIM + cbase];
            float qq[4] = {qf.x, qf.y, qf.z, qf.w};
            float ss[4] = {sf.x, sf.y, sf.z, sf.w};
            #pragma unroll
            for (int a = 0; a < 4; a++)
                #pragma unroll
                for (int b = 0; b < 4; b++)
                    acc[a][b] += qq[a] * ss[b];
        }
        #pragma unroll
        for (int a = 0; a < 4; a++) {
            float inv = sDen[rbase + a];
            *(float4*)&Og[base + (size_t)(rbase + a) * DDIM + cbase] =
                make_float4(acc[a][0] * inv, acc[a][1] * inv,
                            acc[a][2] * inv, acc[a][3] * inv);
        }
    }
}

// ---------------------------------------------------------------------------
extern "C" void kernel_launch(void* const* d_in, const int* in_sizes, int n_in,
                              void* d_out, int out_size) {
    const float* Q = (const float*)d_in[0];
    const float* K = (const float*)d_in[1];
    const float* V = (const float*)d_in[2];
    float* O = (float*)d_out;

    const int SMEM1 = 2 * CHK * DDIM * (int)sizeof(float);                   // 32 KB
    const int SMEM3 = (2 * DDIM * ST + CHK * DDIM + DDIM * DDIM +
                       CHK * ST + DDIM + CHK) * (int)sizeof(float);          // ~85.5 KB

    static int inited = 0;
    if (!inited) {
        cudaFuncSetAttribute(lin_phase1, cudaFuncAttributeMaxDynamicSharedMemorySize, SMEM1);
        cudaFuncSetAttribute(lin_phase3, cudaFuncAttributeMaxDynamicSharedMemorySize, SMEM3);
        inited = 1;
    }

    lin_phase1<<<NB, 256, SMEM1>>>(K, V);
    lin_phase2<<<HNUM * 8, 512>>>();
    lin_phase3<<<NB, 256, SMEM3>>>(Q, K, V, O);
}